// round 7
// baseline (speedup 1.0000x reference)
#include <cuda_runtime.h>
#include <cuda_fp16.h>
#include <cstdint>

// ---------------------------------------------------------------------------
// VLMSpatialHead via mma.sync (HMMA fp16) on sm_103:
//   X   = hidden[flat_idx]              [N_TOK, 2048]
//   Hm  = mish(X @ W1^T + b1)           [N_TOK, 1024]
//   S   = Hm @ W2^T + b2                [N_TOK, 256]
//   out = segment_sum(S, segment_ids)   [N_IMG, 256]
// R5: fp16 2-product scheme — activations split hi/lo fp16 (exact),
//     weights single fp16 (error 2^-12 stat) -> 2/3 the MMA work of the
//     bf16 3-product scheme. 4-stage cp.async ring, hoisted addressing.
// ---------------------------------------------------------------------------

#define NTOK_MAX 32768
#define HDIM     2048
#define DMID     1024
#define DOUT     256
#define PCHUNK   16

// ---------------- scratch (device globals; no allocs) ----------------
__device__ __align__(256) __half g_Xhi[(size_t)NTOK_MAX * HDIM];
__device__ __align__(256) __half g_Xlo[(size_t)NTOK_MAX * HDIM];
__device__ __align__(256) __half g_W1h[(size_t)DMID * HDIM];
__device__ __align__(256) __half g_W2h[(size_t)DOUT * DMID];
__device__ __align__(256) __half g_Hhi[(size_t)NTOK_MAX * DMID];
__device__ __align__(256) __half g_Hlo[(size_t)NTOK_MAX * DMID];
__device__ __align__(256) float  g_S  [(size_t)NTOK_MAX * DOUT];
__device__ __align__(256) float  g_P  [64 * PCHUNK * DOUT];

// ---------------- helpers ----------------
__device__ __forceinline__ uint32_t smem_u32(const void* p) {
    uint32_t a;
    asm("{ .reg .u64 t; cvta.to.shared.u64 t, %1; cvt.u32.u64 %0, t; }" : "=r"(a) : "l"(p));
    return a;
}
__device__ __forceinline__ void cp16(uint32_t saddr, const void* gaddr) {
    asm volatile("cp.async.cg.shared.global [%0], [%1], 16;" :: "r"(saddr), "l"(gaddr));
}
#define CP_COMMIT() asm volatile("cp.async.commit_group;" ::: "memory")
#define CP_WAIT2()  asm volatile("cp.async.wait_group 2;"  ::: "memory")

#define LDSM4(r0, r1, r2, r3, a) \
    asm volatile("ldmatrix.sync.aligned.m8n8.x4.shared.b16 {%0,%1,%2,%3}, [%4];" \
                 : "=r"(r0), "=r"(r1), "=r"(r2), "=r"(r3) : "r"(a))

#define MMA16816(c, a, b) \
    asm volatile("mma.sync.aligned.m16n8k16.row.col.f32.f16.f16.f32 " \
                 "{%0,%1,%2,%3}, {%4,%5,%6,%7}, {%8,%9}, {%0,%1,%2,%3};" \
                 : "+f"((c)[0]), "+f"((c)[1]), "+f"((c)[2]), "+f"((c)[3]) \
                 : "r"((a)[0]), "r"((a)[1]), "r"((a)[2]), "r"((a)[3]), \
                   "r"((b)[0]), "r"((b)[1]))

__device__ __forceinline__ float mish_acc(float x) {
    // mish(x) = x * u/(u+2), u = e^x (e^x + 2); precise expf for accuracy.
    float t = expf(fminf(x, 20.0f));
    float u = t * (t + 2.0f);
    return x * (u / (u + 2.0f));
}

// ---------------- fp32 -> fp16 hi/lo split (optional gather + pad) ----
// If lo == nullptr, only the hi (rounded) half is written (for weights).
__global__ void __launch_bounds__(256)
split_fp16(const float* __restrict__ src, const int* __restrict__ gidx,
           int rows_valid, long long total4, int K,
           __half* __restrict__ hi, __half* __restrict__ lo)
{
    long long i = (long long)blockIdx.x * 256 + threadIdx.x;
    if (i >= total4) return;
    int k4 = K >> 2;
    int row = (int)(i / k4);
    int c   = (int)(i % k4);
    float4 v = make_float4(0.f, 0.f, 0.f, 0.f);
    if (row < rows_valid) {
        size_t srow = gidx ? (size_t)gidx[row] : (size_t)row;
        v = *(const float4*)(src + srow * (size_t)K + (size_t)c * 4);
    }
    float vv[4] = {v.x, v.y, v.z, v.w};
    __half h[4];
    #pragma unroll
    for (int j = 0; j < 4; j++) h[j] = __float2half(vv[j]);
    __half2 h0 = __halves2half2(h[0], h[1]);
    __half2 h1 = __halves2half2(h[2], h[3]);
    uint2 hp;
    hp.x = *(uint32_t*)&h0; hp.y = *(uint32_t*)&h1;
    *(uint2*)(hi + i * 4) = hp;
    if (lo) {
        __half l[4];
        #pragma unroll
        for (int j = 0; j < 4; j++) l[j] = __float2half(vv[j] - __half2float(h[j]));
        __half2 l0 = __halves2half2(l[0], l[1]);
        __half2 l1 = __halves2half2(l[2], l[3]);
        uint2 lp;
        lp.x = *(uint32_t*)&l0; lp.y = *(uint32_t*)&l1;
        *(uint2*)(lo + i * 4) = lp;
    }
}

// ---------------- HMMA GEMM: 128x128 CTA tile, BK=64, 4-stage cp.async ----
// Stage layout (48KB): [Ahi 16K][Alo 16K][W 16K], each 128 rows x 128B,
// full SW128 swizzle (quad ^= row&7).
#define STAGE_B   49152
#define GEMM_SMEM (4 * STAGE_B)

template<int KD, bool MISH>
__global__ void __launch_bounds__(256, 1)
mma_gemm(const __half* __restrict__ Ahi, const __half* __restrict__ Alo,
         const __half* __restrict__ W,
         const float* __restrict__ bias,
         __half* __restrict__ OHi, __half* __restrict__ OLo,
         float* __restrict__ OF, int ldo)
{
    extern __shared__ __align__(128) char sm[];
    const uint32_t sbase = smem_u32(sm);
    const int tid  = threadIdx.x;
    const int lane = tid & 31;
    const int warp = tid >> 5;
    const int wm   = warp >> 2;   // 0..1 -> 64 rows
    const int wn   = warp & 3;    // 0..3 -> 32 cols
    const int bm   = blockIdx.y * 128;
    const int bn   = blockIdx.x * 128;

    constexpr int NCH = KD / 64;        // K chunks of 64 fp16 (128B)
    const int krow4   = KD / 8;         // row stride in uint4

    // ---- hoisted cp.async addressing: 12 chunks/thread/stage ----
    const uint4* gp[12];
    uint32_t     so[12];
    {
        const uint4* srcs[3] = { (const uint4*)Ahi, (const uint4*)Alo, (const uint4*)W };
        #pragma unroll
        for (int m = 0; m < 3; m++) {
            const int rb = (m < 2) ? bm : bn;
            #pragma unroll
            for (int it = 0; it < 4; it++) {
                int e = tid + it * 256, r = e >> 3, q = e & 7;
                int j = m * 4 + it;
                gp[j] = srcs[m] + (size_t)(rb + r) * krow4 + q;
                so[j] = (uint32_t)(m * 16384 + r * 128 + ((q ^ (r & 7)) << 4));
            }
        }
    }
    // ---- hoisted ldmatrix row bases ----
    uint32_t aRowOff[4]; int aX7[4];
    #pragma unroll
    for (int mt = 0; mt < 4; mt++) {
        int r = wm * 64 + mt * 16 + (lane & 15);
        aRowOff[mt] = (uint32_t)(r * 128); aX7[mt] = r & 7;
    }
    uint32_t bRowOff[2]; int bX7[2];
    #pragma unroll
    for (int p = 0; p < 2; p++) {
        int r = wn * 32 + p * 16 + (lane & 15);
        bRowOff[p] = (uint32_t)(r * 128); bX7[p] = r & 7;
    }
    const int lh = lane >> 4;

    float acc[4][4][4];
    #pragma unroll
    for (int i = 0; i < 4; i++)
        #pragma unroll
        for (int j = 0; j < 4; j++)
            #pragma unroll
            for (int k = 0; k < 4; k++) acc[i][j][k] = 0.0f;

    auto load_stage = [&](int ch, uint32_t st) {
        #pragma unroll
        for (int j = 0; j < 12; j++) cp16(st + so[j], gp[j] + ch * 8);
    };

    // prologue: 3 stages in flight
    load_stage(0, sbase);                            CP_COMMIT();
    if (NCH > 1) load_stage(1, sbase + STAGE_B);     CP_COMMIT();
    if (NCH > 2) load_stage(2, sbase + 2 * STAGE_B); CP_COMMIT();

    for (int i = 0; i < NCH; ++i) {
        CP_WAIT2();
        __syncthreads();
        const uint32_t st = sbase + (uint32_t)(i & 3) * STAGE_B;

        #pragma unroll
        for (int ks = 0; ks < 4; ks++) {           // four K16 steps per chunk
            const int qb = ks * 2 + lh;

            uint32_t ah[4][4], al[4][4];
            #pragma unroll
            for (int mt = 0; mt < 4; mt++) {
                uint32_t x = (uint32_t)((qb ^ aX7[mt]) << 4);
                LDSM4(ah[mt][0], ah[mt][1], ah[mt][2], ah[mt][3], st + aRowOff[mt] + x);
                LDSM4(al[mt][0], al[mt][1], al[mt][2], al[mt][3], st + 16384 + aRowOff[mt] + x);
            }
            uint32_t bh[4][2];
            #pragma unroll
            for (int p = 0; p < 2; p++) {
                uint32_t off = bRowOff[p] + (uint32_t)((qb ^ bX7[p]) << 4);
                uint32_t t0, t1, t2, t3;
                LDSM4(t0, t1, t2, t3, st + 32768 + off);
                bh[p*2][0] = t0; bh[p*2+1][0] = t1; bh[p*2][1] = t2; bh[p*2+1][1] = t3;
            }
            // product-major: 16 independent accumulators between reuse
            #pragma unroll
            for (int mt = 0; mt < 4; mt++)
                #pragma unroll
                for (int nt = 0; nt < 4; nt++)
                    MMA16816(acc[mt][nt], ah[mt], bh[nt]);
            #pragma unroll
            for (int mt = 0; mt < 4; mt++)
                #pragma unroll
                for (int nt = 0; nt < 4; nt++)
                    MMA16816(acc[mt][nt], al[mt], bh[nt]);
        }

        int nxt = i + 3;
        if (nxt < NCH) load_stage(nxt, sbase + (uint32_t)(nxt & 3) * STAGE_B);
        CP_COMMIT();
    }

    // -------- epilogue --------
    const int g  = lane >> 2;
    const int c2 = (lane & 3) * 2;
    #pragma unroll
    for (int nt = 0; nt < 4; nt++) {
        const int col = bn + wn * 32 + nt * 8 + c2;
        float2 bv = __ldg((const float2*)(bias + col));
        #pragma unroll
        for (int mt = 0; mt < 4; mt++) {
            const int row0 = bm + wm * 64 + mt * 16 + g;
            float v0 = acc[mt][nt][0] + bv.x;
            float v1 = acc[mt][nt][1] + bv.y;
            float v2 = acc[mt][nt][2] + bv.x;
            float v3 = acc[mt][nt][3] + bv.y;
            if (MISH) {
                v0 = mish_acc(v0); v1 = mish_acc(v1);
                v2 = mish_acc(v2); v3 = mish_acc(v3);
                __half h0 = __float2half(v0), h1 = __float2half(v1);
                __half h2 = __float2half(v2), h3 = __float2half(v3);
                __half2 hv0 = __halves2half2(h0, h1);
                __half2 hv1 = __halves2half2(h2, h3);
                __half2 lv0 = __halves2half2(
                    __float2half(v0 - __half2float(h0)),
                    __float2half(v1 - __half2float(h1)));
                __half2 lv1 = __halves2half2(
                    __float2half(v2 - __half2float(h2)),
                    __float2half(v3 - __half2float(h3)));
                *(__half2*)(OHi + (size_t)row0 * ldo + col)       = hv0;
                *(__half2*)(OHi + (size_t)(row0 + 8) * ldo + col) = hv1;
                *(__half2*)(OLo + (size_t)row0 * ldo + col)       = lv0;
                *(__half2*)(OLo + (size_t)(row0 + 8) * ldo + col) = lv1;
            } else {
                *(float2*)(OF + (size_t)row0 * ldo + col)       = make_float2(v0, v1);
                *(float2*)(OF + (size_t)(row0 + 8) * ldo + col) = make_float2(v2, v3);
            }
        }
    }
}

// ---------------- deterministic 2-phase segment pooling ----------------
__global__ void __launch_bounds__(1024)
pool_partial(const float* __restrict__ S, const int* __restrict__ seg,
             int n_tok, float* __restrict__ P)
{
    const int gseg = blockIdx.x;
    const int sub  = threadIdx.x >> 8;
    const int col  = threadIdx.x & 255;
    const int chunk = blockIdx.y * 4 + sub;

    int lo = 0, hi = n_tok;
    while (lo < hi) { int m = (lo + hi) >> 1; if (seg[m] < gseg) lo = m + 1; else hi = m; }
    const int s = lo;
    lo = s; hi = n_tok;
    while (lo < hi) { int m = (lo + hi) >> 1; if (seg[m] < gseg + 1) lo = m + 1; else hi = m; }
    const int e = lo;

    const int len = e - s;
    const int L = (len + PCHUNK - 1) / PCHUNK;
    const int cs = s + chunk * L;
    const int ce = min(cs + L, e);

    float a0 = 0.f, a1 = 0.f, a2 = 0.f, a3 = 0.f;
    int t = cs;
    for (; t + 4 <= ce; t += 4) {
        a0 += S[(size_t)(t + 0) * DOUT + col];
        a1 += S[(size_t)(t + 1) * DOUT + col];
        a2 += S[(size_t)(t + 2) * DOUT + col];
        a3 += S[(size_t)(t + 3) * DOUT + col];
    }
    float acc = (a0 + a1) + (a2 + a3);
    for (; t < ce; t++) acc += S[(size_t)t * DOUT + col];
    P[((size_t)gseg * PCHUNK + chunk) * DOUT + col] = acc;
}

__global__ void __launch_bounds__(256)
pool_final(const float* __restrict__ P, float* __restrict__ out)
{
    const int gseg = blockIdx.x, col = threadIdx.x;
    float acc = 0.f;
    #pragma unroll
    for (int c = 0; c < PCHUNK; c++)
        acc += P[((size_t)gseg * PCHUNK + c) * DOUT + col];
    out[(size_t)gseg * DOUT + col] = acc;
}

// ---------------- launch ----------------
extern "C" void kernel_launch(void* const* d_in, const int* in_sizes, int n_in,
                              void* d_out, int out_size)
{
    const float* hidden   = (const float*)d_in[0];
    const float* W1       = (const float*)d_in[1];
    const float* b1       = (const float*)d_in[2];
    const float* W2       = (const float*)d_in[3];
    const float* b2       = (const float*)d_in[4];
    const int*   flat_idx = (const int*)d_in[5];
    const int*   seg      = (const int*)d_in[6];
    float*       out      = (float*)d_out;

    const int n_tok = in_sizes[5];
    const int n_img = out_size / DOUT;
    const int mpad  = ((n_tok + 127) / 128) * 128;

    __half *xhi, *xlo, *w1h, *w2h, *hhi, *hlo;
    float *sbuf, *pbuf;
    cudaGetSymbolAddress((void**)&xhi, g_Xhi);
    cudaGetSymbolAddress((void**)&xlo, g_Xlo);
    cudaGetSymbolAddress((void**)&w1h, g_W1h);
    cudaGetSymbolAddress((void**)&w2h, g_W2h);
    cudaGetSymbolAddress((void**)&hhi, g_Hhi);
    cudaGetSymbolAddress((void**)&hlo, g_Hlo);
    cudaGetSymbolAddress((void**)&sbuf, g_S);
    cudaGetSymbolAddress((void**)&pbuf, g_P);

    cudaFuncSetAttribute(mma_gemm<HDIM, true>,
                         cudaFuncAttributeMaxDynamicSharedMemorySize, GEMM_SMEM);
    cudaFuncSetAttribute(mma_gemm<DMID, false>,
                         cudaFuncAttributeMaxDynamicSharedMemorySize, GEMM_SMEM);

    // 1) splits / conversions
    {
        long long t4 = (long long)mpad * HDIM / 4;
        split_fp16<<<(unsigned)((t4 + 255) / 256), 256>>>(hidden, flat_idx, n_tok, t4, HDIM, xhi, xlo);
        long long w1t = (long long)DMID * HDIM / 4;
        split_fp16<<<(unsigned)((w1t + 255) / 256), 256>>>(W1, nullptr, DMID, w1t, HDIM, w1h, nullptr);
        long long w2t = (long long)DOUT * DMID / 4;
        split_fp16<<<(unsigned)((w2t + 255) / 256), 256>>>(W2, nullptr, DOUT, w2t, DMID, w2h, nullptr);
    }
    // 2) GEMM1 + bias + mish -> H (fp16 hi/lo)
    {
        dim3 g(DMID / 128, mpad / 128);
        mma_gemm<HDIM, true><<<g, 256, GEMM_SMEM>>>(xhi, xlo, w1h, b1,
                                                    hhi, hlo, nullptr, DMID);
    }
    // 3) GEMM2 + bias -> S (fp32)
    {
        dim3 g(DOUT / 128, mpad / 128);
        mma_gemm<DMID, false><<<g, 256, GEMM_SMEM>>>(hhi, hlo, w2h, b2,
                                                     nullptr, nullptr, sbuf, DOUT);
    }
    // 4) pooling (2-phase deterministic)
    {
        dim3 gp(n_img, PCHUNK / 4);
        pool_partial<<<gp, 1024>>>(sbuf, seg, n_tok, pbuf);
        pool_final<<<n_img, 256>>>(pbuf, out);
    }
}

// round 8
// speedup vs baseline: 1.0883x; 1.0883x over previous
#include <cuda_runtime.h>
#include <cuda_fp16.h>
#include <cstdint>

// ---------------------------------------------------------------------------
// VLMSpatialHead via mma.sync (HMMA fp16) on sm_103:
//   X   = hidden[flat_idx]              [N_TOK, 2048]
//   Hm  = mish(X @ W1^T + b1)           [N_TOK, 1024]
//   S   = Hm @ W2^T + b2                [N_TOK, 256]
//   out = segment_sum(S, segment_ids)   [N_IMG, 256]
// fp16 2-product scheme (act split hi/lo, weight single fp16).
// R8: 512-thread CTA, 128x256 tile (16 warps x [32x64]) -> 4 warps/SMSP,
//     3-stage 64K cp.async ring, hoisted addressing.
// ---------------------------------------------------------------------------

#define NTOK_MAX 32768
#define HDIM     2048
#define DMID     1024
#define DOUT     256
#define PCHUNK   16

// ---------------- scratch (device globals; no allocs) ----------------
__device__ __align__(256) __half g_Xhi[(size_t)NTOK_MAX * HDIM];
__device__ __align__(256) __half g_Xlo[(size_t)NTOK_MAX * HDIM];
__device__ __align__(256) __half g_W1h[(size_t)DMID * HDIM];
__device__ __align__(256) __half g_W2h[(size_t)DOUT * DMID];
__device__ __align__(256) __half g_Hhi[(size_t)NTOK_MAX * DMID];
__device__ __align__(256) __half g_Hlo[(size_t)NTOK_MAX * DMID];
__device__ __align__(256) float  g_S  [(size_t)NTOK_MAX * DOUT];
__device__ __align__(256) float  g_P  [64 * PCHUNK * DOUT];

// ---------------- helpers ----------------
__device__ __forceinline__ uint32_t smem_u32(const void* p) {
    uint32_t a;
    asm("{ .reg .u64 t; cvta.to.shared.u64 t, %1; cvt.u32.u64 %0, t; }" : "=r"(a) : "l"(p));
    return a;
}
__device__ __forceinline__ void cp16(uint32_t saddr, const void* gaddr) {
    asm volatile("cp.async.cg.shared.global [%0], [%1], 16;" :: "r"(saddr), "l"(gaddr));
}
#define CP_COMMIT() asm volatile("cp.async.commit_group;" ::: "memory")
#define CP_WAIT1()  asm volatile("cp.async.wait_group 1;"  ::: "memory")

#define LDSM4(r0, r1, r2, r3, a) \
    asm volatile("ldmatrix.sync.aligned.m8n8.x4.shared.b16 {%0,%1,%2,%3}, [%4];" \
                 : "=r"(r0), "=r"(r1), "=r"(r2), "=r"(r3) : "r"(a))

#define MMA16816(c, a, b) \
    asm volatile("mma.sync.aligned.m16n8k16.row.col.f32.f16.f16.f32 " \
                 "{%0,%1,%2,%3}, {%4,%5,%6,%7}, {%8,%9}, {%0,%1,%2,%3};" \
                 : "+f"((c)[0]), "+f"((c)[1]), "+f"((c)[2]), "+f"((c)[3]) \
                 : "r"((a)[0]), "r"((a)[1]), "r"((a)[2]), "r"((a)[3]), \
                   "r"((b)[0]), "r"((b)[1]))

__device__ __forceinline__ float mish_acc(float x) {
    float t = expf(fminf(x, 20.0f));
    float u = t * (t + 2.0f);
    return x * (u / (u + 2.0f));
}

// ---------------- fp32 -> fp16 hi/lo split (optional gather + pad) ----
__global__ void __launch_bounds__(256)
split_fp16(const float* __restrict__ src, const int* __restrict__ gidx,
           int rows_valid, long long total4, int K,
           __half* __restrict__ hi, __half* __restrict__ lo)
{
    long long i = (long long)blockIdx.x * 256 + threadIdx.x;
    if (i >= total4) return;
    int k4 = K >> 2;
    int row = (int)(i / k4);
    int c   = (int)(i % k4);
    float4 v = make_float4(0.f, 0.f, 0.f, 0.f);
    if (row < rows_valid) {
        size_t srow = gidx ? (size_t)gidx[row] : (size_t)row;
        v = *(const float4*)(src + srow * (size_t)K + (size_t)c * 4);
    }
    float vv[4] = {v.x, v.y, v.z, v.w};
    __half h[4];
    #pragma unroll
    for (int j = 0; j < 4; j++) h[j] = __float2half(vv[j]);
    __half2 h0 = __halves2half2(h[0], h[1]);
    __half2 h1 = __halves2half2(h[2], h[3]);
    uint2 hp;
    hp.x = *(uint32_t*)&h0; hp.y = *(uint32_t*)&h1;
    *(uint2*)(hi + i * 4) = hp;
    if (lo) {
        __half l[4];
        #pragma unroll
        for (int j = 0; j < 4; j++) l[j] = __float2half(vv[j] - __half2float(h[j]));
        __half2 l0 = __halves2half2(l[0], l[1]);
        __half2 l1 = __halves2half2(l[2], l[3]);
        uint2 lp;
        lp.x = *(uint32_t*)&l0; lp.y = *(uint32_t*)&l1;
        *(uint2*)(lo + i * 4) = lp;
    }
}

// ---------------- HMMA GEMM: 128x256 CTA tile, BK=64, 3-stage ring ----
// Stage (64KB): [Ahi 16K @0][Alo 16K @16384][W 32K @32768],
// A rows 128 x 128B, W rows 256 x 128B, SW128 swizzle (quad ^= row&7).
#define STAGE_B   65536
#define GEMM_SMEM (3 * STAGE_B)

template<int KD, bool MISH>
__global__ void __launch_bounds__(512, 1)
mma_gemm(const __half* __restrict__ Ahi, const __half* __restrict__ Alo,
         const __half* __restrict__ W,
         const float* __restrict__ bias,
         __half* __restrict__ OHi, __half* __restrict__ OLo,
         float* __restrict__ OF, int ldo)
{
    extern __shared__ __align__(128) char sm[];
    const uint32_t sbase = smem_u32(sm);
    const int tid  = threadIdx.x;
    const int lane = tid & 31;
    const int warp = tid >> 5;
    const int wm   = warp >> 2;   // 0..3 -> 32 rows each
    const int wn   = warp & 3;    // 0..3 -> 64 cols each
    const int bm   = blockIdx.y * 128;
    const int bn   = blockIdx.x * 256;

    constexpr int NCH = KD / 64;        // K chunks of 64 fp16 (128B)
    const int krow4   = KD / 8;         // row stride in uint4

    // ---- hoisted cp.async addressing: 8 chunks/thread/stage ----
    const uint4* gp[8];
    uint32_t     so[8];
    {
        // Ahi: 2, Alo: 2, W: 4
        #pragma unroll
        for (int it = 0; it < 2; it++) {
            int e = tid + it * 512, r = e >> 3, q = e & 7;
            gp[it]     = (const uint4*)Ahi + (size_t)(bm + r) * krow4 + q;
            so[it]     = (uint32_t)(r * 128 + ((q ^ (r & 7)) << 4));
            gp[2 + it] = (const uint4*)Alo + (size_t)(bm + r) * krow4 + q;
            so[2 + it] = so[it] + 16384;
        }
        #pragma unroll
        for (int it = 0; it < 4; it++) {
            int e = tid + it * 512, r = e >> 3, q = e & 7;
            gp[4 + it] = (const uint4*)W + (size_t)(bn + r) * krow4 + q;
            so[4 + it] = (uint32_t)(32768 + r * 128 + ((q ^ (r & 7)) << 4));
        }
    }
    // ---- hoisted ldmatrix row bases ----
    uint32_t aRowOff[2]; int aX7[2];
    #pragma unroll
    for (int mt = 0; mt < 2; mt++) {
        int r = wm * 32 + mt * 16 + (lane & 15);
        aRowOff[mt] = (uint32_t)(r * 128); aX7[mt] = r & 7;
    }
    uint32_t bRowOff[4]; int bX7[4];
    #pragma unroll
    for (int p = 0; p < 4; p++) {
        int r = wn * 64 + p * 16 + (lane & 15);
        bRowOff[p] = (uint32_t)(32768 + r * 128); bX7[p] = r & 7;
    }
    const int lh = lane >> 4;

    float acc[2][8][4];
    #pragma unroll
    for (int i = 0; i < 2; i++)
        #pragma unroll
        for (int j = 0; j < 8; j++)
            #pragma unroll
            for (int k = 0; k < 4; k++) acc[i][j][k] = 0.0f;

    auto load_stage = [&](int ch, uint32_t st) {
        #pragma unroll
        for (int j = 0; j < 8; j++) cp16(st + so[j], gp[j] + ch * 8);
    };

    // prologue: 2 stages in flight
    load_stage(0, sbase);                        CP_COMMIT();
    if (NCH > 1) load_stage(1, sbase + STAGE_B); CP_COMMIT();

    int slot = 0, lslot = 2;
    for (int i = 0; i < NCH; ++i) {
        CP_WAIT1();
        __syncthreads();
        const uint32_t st = sbase + (uint32_t)slot * STAGE_B;

        // kick off load of chunk i+2 into the slot freed at iteration i-1
        int nxt = i + 2;
        if (nxt < NCH) load_stage(nxt, sbase + (uint32_t)lslot * STAGE_B);
        CP_COMMIT();

        #pragma unroll
        for (int ks = 0; ks < 4; ks++) {           // four K16 steps per chunk
            const int qb = ks * 2 + lh;

            uint32_t ah[2][4], al[2][4];
            #pragma unroll
            for (int mt = 0; mt < 2; mt++) {
                uint32_t x = (uint32_t)((qb ^ aX7[mt]) << 4);
                LDSM4(ah[mt][0], ah[mt][1], ah[mt][2], ah[mt][3], st + aRowOff[mt] + x);
                LDSM4(al[mt][0], al[mt][1], al[mt][2], al[mt][3], st + 16384 + aRowOff[mt] + x);
            }
            uint32_t bh[8][2];
            #pragma unroll
            for (int p = 0; p < 4; p++) {
                uint32_t off = st + bRowOff[p] + (uint32_t)((qb ^ bX7[p]) << 4);
                uint32_t t0, t1, t2, t3;
                LDSM4(t0, t1, t2, t3, off);
                bh[p*2][0] = t0; bh[p*2+1][0] = t1; bh[p*2][1] = t2; bh[p*2+1][1] = t3;
            }
            // product-major: 16 independent accumulators between reuse
            #pragma unroll
            for (int mt = 0; mt < 2; mt++)
                #pragma unroll
                for (int nt = 0; nt < 8; nt++)
                    MMA16816(acc[mt][nt], ah[mt], bh[nt]);
            #pragma unroll
            for (int mt = 0; mt < 2; mt++)
                #pragma unroll
                for (int nt = 0; nt < 8; nt++)
                    MMA16816(acc[mt][nt], al[mt], bh[nt]);
        }

        slot  = (slot == 2)  ? 0 : slot + 1;
        lslot = (lslot == 2) ? 0 : lslot + 1;
    }

    // -------- epilogue --------
    const int g  = lane >> 2;
    const int c2 = (lane & 3) * 2;
    #pragma unroll
    for (int nt = 0; nt < 8; nt++) {
        const int col = bn + wn * 64 + nt * 8 + c2;
        float2 bv = __ldg((const float2*)(bias + col));
        #pragma unroll
        for (int mt = 0; mt < 2; mt++) {
            const int row0 = bm + wm * 32 + mt * 16 + g;
            float v0 = acc[mt][nt][0] + bv.x;
            float v1 = acc[mt][nt][1] + bv.y;
            float v2 = acc[mt][nt][2] + bv.x;
            float v3 = acc[mt][nt][3] + bv.y;
            if (MISH) {
                v0 = mish_acc(v0); v1 = mish_acc(v1);
                v2 = mish_acc(v2); v3 = mish_acc(v3);
                __half h0 = __float2half(v0), h1 = __float2half(v1);
                __half h2 = __float2half(v2), h3 = __float2half(v3);
                __half2 hv0 = __halves2half2(h0, h1);
                __half2 hv1 = __halves2half2(h2, h3);
                __half2 lv0 = __halves2half2(
                    __float2half(v0 - __half2float(h0)),
                    __float2half(v1 - __half2float(h1)));
                __half2 lv1 = __halves2half2(
                    __float2half(v2 - __half2float(h2)),
                    __float2half(v3 - __half2float(h3)));
                *(__half2*)(OHi + (size_t)row0 * ldo + col)       = hv0;
                *(__half2*)(OHi + (size_t)(row0 + 8) * ldo + col) = hv1;
                *(__half2*)(OLo + (size_t)row0 * ldo + col)       = lv0;
                *(__half2*)(OLo + (size_t)(row0 + 8) * ldo + col) = lv1;
            } else {
                *(float2*)(OF + (size_t)row0 * ldo + col)       = make_float2(v0, v1);
                *(float2*)(OF + (size_t)(row0 + 8) * ldo + col) = make_float2(v2, v3);
            }
        }
    }
}

// ---------------- deterministic 2-phase segment pooling ----------------
__global__ void __launch_bounds__(1024)
pool_partial(const float* __restrict__ S, const int* __restrict__ seg,
             int n_tok, float* __restrict__ P)
{
    const int gseg = blockIdx.x;
    const int sub  = threadIdx.x >> 8;
    const int col  = threadIdx.x & 255;
    const int chunk = blockIdx.y * 4 + sub;

    int lo = 0, hi = n_tok;
    while (lo < hi) { int m = (lo + hi) >> 1; if (seg[m] < gseg) lo = m + 1; else hi = m; }
    const int s = lo;
    lo = s; hi = n_tok;
    while (lo < hi) { int m = (lo + hi) >> 1; if (seg[m] < gseg + 1) lo = m + 1; else hi = m; }
    const int e = lo;

    const int len = e - s;
    const int L = (len + PCHUNK - 1) / PCHUNK;
    const int cs = s + chunk * L;
    const int ce = min(cs + L, e);

    float a0 = 0.f, a1 = 0.f, a2 = 0.f, a3 = 0.f;
    int t = cs;
    for (; t + 4 <= ce; t += 4) {
        a0 += S[(size_t)(t + 0) * DOUT + col];
        a1 += S[(size_t)(t + 1) * DOUT + col];
        a2 += S[(size_t)(t + 2) * DOUT + col];
        a3 += S[(size_t)(t + 3) * DOUT + col];
    }
    float acc = (a0 + a1) + (a2 + a3);
    for (; t < ce; t++) acc += S[(size_t)t * DOUT + col];
    P[((size_t)gseg * PCHUNK + chunk) * DOUT + col] = acc;
}

__global__ void __launch_bounds__(256)
pool_final(const float* __restrict__ P, float* __restrict__ out)
{
    const int gseg = blockIdx.x, col = threadIdx.x;
    float acc = 0.f;
    #pragma unroll
    for (int c = 0; c < PCHUNK; c++)
        acc += P[((size_t)gseg * PCHUNK + c) * DOUT + col];
    out[(size_t)gseg * DOUT + col] = acc;
}

// ---------------- launch ----------------
extern "C" void kernel_launch(void* const* d_in, const int* in_sizes, int n_in,
                              void* d_out, int out_size)
{
    const float* hidden   = (const float*)d_in[0];
    const float* W1       = (const float*)d_in[1];
    const float* b1       = (const float*)d_in[2];
    const float* W2       = (const float*)d_in[3];
    const float* b2       = (const float*)d_in[4];
    const int*   flat_idx = (const int*)d_in[5];
    const int*   seg      = (const int*)d_in[6];
    float*       out      = (float*)d_out;

    const int n_tok = in_sizes[5];
    const int n_img = out_size / DOUT;
    const int mpad  = ((n_tok + 127) / 128) * 128;

    __half *xhi, *xlo, *w1h, *w2h, *hhi, *hlo;
    float *sbuf, *pbuf;
    cudaGetSymbolAddress((void**)&xhi, g_Xhi);
    cudaGetSymbolAddress((void**)&xlo, g_Xlo);
    cudaGetSymbolAddress((void**)&w1h, g_W1h);
    cudaGetSymbolAddress((void**)&w2h, g_W2h);
    cudaGetSymbolAddress((void**)&hhi, g_Hhi);
    cudaGetSymbolAddress((void**)&hlo, g_Hlo);
    cudaGetSymbolAddress((void**)&sbuf, g_S);
    cudaGetSymbolAddress((void**)&pbuf, g_P);

    cudaFuncSetAttribute(mma_gemm<HDIM, true>,
                         cudaFuncAttributeMaxDynamicSharedMemorySize, GEMM_SMEM);
    cudaFuncSetAttribute(mma_gemm<DMID, false>,
                         cudaFuncAttributeMaxDynamicSharedMemorySize, GEMM_SMEM);

    // 1) splits / conversions
    {
        long long t4 = (long long)mpad * HDIM / 4;
        split_fp16<<<(unsigned)((t4 + 255) / 256), 256>>>(hidden, flat_idx, n_tok, t4, HDIM, xhi, xlo);
        long long w1t = (long long)DMID * HDIM / 4;
        split_fp16<<<(unsigned)((w1t + 255) / 256), 256>>>(W1, nullptr, DMID, w1t, HDIM, w1h, nullptr);
        long long w2t = (long long)DOUT * DMID / 4;
        split_fp16<<<(unsigned)((w2t + 255) / 256), 256>>>(W2, nullptr, DOUT, w2t, DMID, w2h, nullptr);
    }
    // 2) GEMM1 + bias + mish -> H (fp16 hi/lo)
    {
        dim3 g(DMID / 256, mpad / 128);
        mma_gemm<HDIM, true><<<g, 512, GEMM_SMEM>>>(xhi, xlo, w1h, b1,
                                                    hhi, hlo, nullptr, DMID);
    }
    // 3) GEMM2 + bias -> S (fp32)
    {
        dim3 g(DOUT / 256, mpad / 128);
        mma_gemm<DMID, false><<<g, 512, GEMM_SMEM>>>(hhi, hlo, w2h, b2,
                                                     nullptr, nullptr, sbuf, DOUT);
    }
    // 4) pooling (2-phase deterministic)
    {
        dim3 gp(n_img, PCHUNK / 4);
        pool_partial<<<gp, 1024>>>(sbuf, seg, n_tok, pbuf);
        pool_final<<<n_img, 256>>>(pbuf, out);
    }
}

// round 9
// speedup vs baseline: 1.8116x; 1.6646x over previous
#include <cuda_runtime.h>
#include <cuda_fp16.h>
#include <cstdint>

// ---------------------------------------------------------------------------
// VLMSpatialHead via mma.sync (HMMA fp16) on sm_103:
//   X   = hidden[flat_idx]              [N_TOK, 2048]
//   Hm  = mish(X @ W1^T + b1)           [N_TOK, 1024]
//   S   = Hm @ W2^T + b2                [N_TOK, 256]
//   out = segment_sum(S, segment_ids)   [N_IMG, 256]
// R9: single-product fp16 GEMMs (X, W, H all rounded to fp16; error budget
//     measured at ~2e-4 per source, gate 1e-3). 512-thread CTA, 128x256 tile,
//     4-stage 48K cp.async ring.
// ---------------------------------------------------------------------------

#define NTOK_MAX 32768
#define HDIM     2048
#define DMID     1024
#define DOUT     256
#define PCHUNK   16

// ---------------- scratch (device globals; no allocs) ----------------
__device__ __align__(256) __half g_X  [(size_t)NTOK_MAX * HDIM];
__device__ __align__(256) __half g_W1h[(size_t)DMID * HDIM];
__device__ __align__(256) __half g_W2h[(size_t)DOUT * DMID];
__device__ __align__(256) __half g_H  [(size_t)NTOK_MAX * DMID];
__device__ __align__(256) float  g_S  [(size_t)NTOK_MAX * DOUT];
__device__ __align__(256) float  g_P  [64 * PCHUNK * DOUT];

// ---------------- helpers ----------------
__device__ __forceinline__ uint32_t smem_u32(const void* p) {
    uint32_t a;
    asm("{ .reg .u64 t; cvta.to.shared.u64 t, %1; cvt.u32.u64 %0, t; }" : "=r"(a) : "l"(p));
    return a;
}
__device__ __forceinline__ void cp16(uint32_t saddr, const void* gaddr) {
    asm volatile("cp.async.cg.shared.global [%0], [%1], 16;" :: "r"(saddr), "l"(gaddr));
}
#define CP_COMMIT() asm volatile("cp.async.commit_group;" ::: "memory")
#define CP_WAIT2()  asm volatile("cp.async.wait_group 2;"  ::: "memory")

#define LDSM4(r0, r1, r2, r3, a) \
    asm volatile("ldmatrix.sync.aligned.m8n8.x4.shared.b16 {%0,%1,%2,%3}, [%4];" \
                 : "=r"(r0), "=r"(r1), "=r"(r2), "=r"(r3) : "r"(a))

#define MMA16816(c, a, b) \
    asm volatile("mma.sync.aligned.m16n8k16.row.col.f32.f16.f16.f32 " \
                 "{%0,%1,%2,%3}, {%4,%5,%6,%7}, {%8,%9}, {%0,%1,%2,%3};" \
                 : "+f"((c)[0]), "+f"((c)[1]), "+f"((c)[2]), "+f"((c)[3]) \
                 : "r"((a)[0]), "r"((a)[1]), "r"((a)[2]), "r"((a)[3]), \
                   "r"((b)[0]), "r"((b)[1]))

__device__ __forceinline__ float mish_acc(float x) {
    float t = expf(fminf(x, 20.0f));
    float u = t * (t + 2.0f);
    return x * (u / (u + 2.0f));
}

// ---------------- fp32 -> fp16 convert (optional gather + pad) ----
__global__ void __launch_bounds__(256)
conv_fp16(const float* __restrict__ src, const int* __restrict__ gidx,
          int rows_valid, long long total4, int K, __half* __restrict__ dst)
{
    long long i = (long long)blockIdx.x * 256 + threadIdx.x;
    if (i >= total4) return;
    int k4 = K >> 2;
    int row = (int)(i / k4);
    int c   = (int)(i % k4);
    float4 v = make_float4(0.f, 0.f, 0.f, 0.f);
    if (row < rows_valid) {
        size_t srow = gidx ? (size_t)gidx[row] : (size_t)row;
        v = *(const float4*)(src + srow * (size_t)K + (size_t)c * 4);
    }
    __half2 h0 = __halves2half2(__float2half(v.x), __float2half(v.y));
    __half2 h1 = __halves2half2(__float2half(v.z), __float2half(v.w));
    uint2 hp;
    hp.x = *(uint32_t*)&h0; hp.y = *(uint32_t*)&h1;
    *(uint2*)(dst + i * 4) = hp;
}

// ---------------- HMMA GEMM: 128x256 CTA tile, BK=64, 4-stage ring ----
// Stage (48KB): [A 16K @0][W 32K @16384],
// A rows 128 x 128B, W rows 256 x 128B, SW128 swizzle (quad ^= row&7).
#define STAGE_B   49152
#define GEMM_SMEM (4 * STAGE_B)

template<int KD, bool MISH>
__global__ void __launch_bounds__(512, 1)
mma_gemm(const __half* __restrict__ A, const __half* __restrict__ W,
         const float* __restrict__ bias,
         __half* __restrict__ OH, float* __restrict__ OF, int ldo)
{
    extern __shared__ __align__(128) char sm[];
    const uint32_t sbase = smem_u32(sm);
    const int tid  = threadIdx.x;
    const int lane = tid & 31;
    const int warp = tid >> 5;
    const int wm   = warp >> 2;   // 0..3 -> 32 rows each
    const int wn   = warp & 3;    // 0..3 -> 64 cols each
    const int bm   = blockIdx.y * 128;
    const int bn   = blockIdx.x * 256;

    constexpr int NCH = KD / 64;        // K chunks of 64 fp16 (128B)
    const int krow4   = KD / 8;         // row stride in uint4

    // ---- hoisted cp.async addressing: 6 chunks/thread/stage ----
    const uint4* gp[6];
    uint32_t     so[6];
    {
        #pragma unroll
        for (int it = 0; it < 2; it++) {          // A: 128 rows x 8 quads
            int e = tid + it * 512, r = e >> 3, q = e & 7;
            gp[it] = (const uint4*)A + (size_t)(bm + r) * krow4 + q;
            so[it] = (uint32_t)(r * 128 + ((q ^ (r & 7)) << 4));
        }
        #pragma unroll
        for (int it = 0; it < 4; it++) {          // W: 256 rows x 8 quads
            int e = tid + it * 512, r = e >> 3, q = e & 7;
            gp[2 + it] = (const uint4*)W + (size_t)(bn + r) * krow4 + q;
            so[2 + it] = (uint32_t)(16384 + r * 128 + ((q ^ (r & 7)) << 4));
        }
    }
    // ---- hoisted ldmatrix row bases ----
    uint32_t aRowOff[2]; int aX7[2];
    #pragma unroll
    for (int mt = 0; mt < 2; mt++) {
        int r = wm * 32 + mt * 16 + (lane & 15);
        aRowOff[mt] = (uint32_t)(r * 128); aX7[mt] = r & 7;
    }
    uint32_t bRowOff[4]; int bX7[4];
    #pragma unroll
    for (int p = 0; p < 4; p++) {
        int r = wn * 64 + p * 16 + (lane & 15);
        bRowOff[p] = (uint32_t)(16384 + r * 128); bX7[p] = r & 7;
    }
    const int lh = lane >> 4;

    float acc[2][8][4];
    #pragma unroll
    for (int i = 0; i < 2; i++)
        #pragma unroll
        for (int j = 0; j < 8; j++)
            #pragma unroll
            for (int k = 0; k < 4; k++) acc[i][j][k] = 0.0f;

    auto load_stage = [&](int ch, uint32_t st) {
        #pragma unroll
        for (int j = 0; j < 6; j++) cp16(st + so[j], gp[j] + ch * 8);
    };

    // prologue: 3 stages in flight
    load_stage(0, sbase);                            CP_COMMIT();
    if (NCH > 1) load_stage(1, sbase + STAGE_B);     CP_COMMIT();
    if (NCH > 2) load_stage(2, sbase + 2 * STAGE_B); CP_COMMIT();

    for (int i = 0; i < NCH; ++i) {
        CP_WAIT2();
        __syncthreads();
        const uint32_t st = sbase + (uint32_t)(i & 3) * STAGE_B;

        // kick load of chunk i+3 into the slot freed last iteration
        int nxt = i + 3;
        if (nxt < NCH) load_stage(nxt, sbase + (uint32_t)(nxt & 3) * STAGE_B);
        CP_COMMIT();

        #pragma unroll
        for (int ks = 0; ks < 4; ks++) {           // four K16 steps per chunk
            const int qb = ks * 2 + lh;

            uint32_t ah[2][4];
            #pragma unroll
            for (int mt = 0; mt < 2; mt++) {
                uint32_t x = (uint32_t)((qb ^ aX7[mt]) << 4);
                LDSM4(ah[mt][0], ah[mt][1], ah[mt][2], ah[mt][3], st + aRowOff[mt] + x);
            }
            uint32_t bh[8][2];
            #pragma unroll
            for (int p = 0; p < 4; p++) {
                uint32_t off = st + bRowOff[p] + (uint32_t)((qb ^ bX7[p]) << 4);
                uint32_t t0, t1, t2, t3;
                LDSM4(t0, t1, t2, t3, off);
                bh[p*2][0] = t0; bh[p*2+1][0] = t1; bh[p*2][1] = t2; bh[p*2+1][1] = t3;
            }
            #pragma unroll
            for (int mt = 0; mt < 2; mt++)
                #pragma unroll
                for (int nt = 0; nt < 8; nt++)
                    MMA16816(acc[mt][nt], ah[mt], bh[nt]);
        }
    }

    // -------- epilogue --------
    const int g  = lane >> 2;
    const int c2 = (lane & 3) * 2;
    #pragma unroll
    for (int nt = 0; nt < 8; nt++) {
        const int col = bn + wn * 64 + nt * 8 + c2;
        float2 bv = __ldg((const float2*)(bias + col));
        #pragma unroll
        for (int mt = 0; mt < 2; mt++) {
            const int row0 = bm + wm * 32 + mt * 16 + g;
            float v0 = acc[mt][nt][0] + bv.x;
            float v1 = acc[mt][nt][1] + bv.y;
            float v2 = acc[mt][nt][2] + bv.x;
            float v3 = acc[mt][nt][3] + bv.y;
            if (MISH) {
                v0 = mish_acc(v0); v1 = mish_acc(v1);
                v2 = mish_acc(v2); v3 = mish_acc(v3);
                __half2 hv0 = __halves2half2(__float2half(v0), __float2half(v1));
                __half2 hv1 = __halves2half2(__float2half(v2), __float2half(v3));
                *(__half2*)(OH + (size_t)row0 * ldo + col)       = hv0;
                *(__half2*)(OH + (size_t)(row0 + 8) * ldo + col) = hv1;
            } else {
                *(float2*)(OF + (size_t)row0 * ldo + col)       = make_float2(v0, v1);
                *(float2*)(OF + (size_t)(row0 + 8) * ldo + col) = make_float2(v2, v3);
            }
        }
    }
}

// ---------------- deterministic 2-phase segment pooling ----------------
__global__ void __launch_bounds__(1024)
pool_partial(const float* __restrict__ S, const int* __restrict__ seg,
             int n_tok, float* __restrict__ P)
{
    const int gseg = blockIdx.x;
    const int sub  = threadIdx.x >> 8;
    const int col  = threadIdx.x & 255;
    const int chunk = blockIdx.y * 4 + sub;

    int lo = 0, hi = n_tok;
    while (lo < hi) { int m = (lo + hi) >> 1; if (seg[m] < gseg) lo = m + 1; else hi = m; }
    const int s = lo;
    lo = s; hi = n_tok;
    while (lo < hi) { int m = (lo + hi) >> 1; if (seg[m] < gseg + 1) lo = m + 1; else hi = m; }
    const int e = lo;

    const int len = e - s;
    const int L = (len + PCHUNK - 1) / PCHUNK;
    const int cs = s + chunk * L;
    const int ce = min(cs + L, e);

    float a0 = 0.f, a1 = 0.f, a2 = 0.f, a3 = 0.f;
    int t = cs;
    for (; t + 4 <= ce; t += 4) {
        a0 += S[(size_t)(t + 0) * DOUT + col];
        a1 += S[(size_t)(t + 1) * DOUT + col];
        a2 += S[(size_t)(t + 2) * DOUT + col];
        a3 += S[(size_t)(t + 3) * DOUT + col];
    }
    float acc = (a0 + a1) + (a2 + a3);
    for (; t < ce; t++) acc += S[(size_t)t * DOUT + col];
    P[((size_t)gseg * PCHUNK + chunk) * DOUT + col] = acc;
}

__global__ void __launch_bounds__(256)
pool_final(const float* __restrict__ P, float* __restrict__ out)
{
    const int gseg = blockIdx.x, col = threadIdx.x;
    float acc = 0.f;
    #pragma unroll
    for (int c = 0; c < PCHUNK; c++)
        acc += P[((size_t)gseg * PCHUNK + c) * DOUT + col];
    out[(size_t)gseg * DOUT + col] = acc;
}

// ---------------- launch ----------------
extern "C" void kernel_launch(void* const* d_in, const int* in_sizes, int n_in,
                              void* d_out, int out_size)
{
    const float* hidden   = (const float*)d_in[0];
    const float* W1       = (const float*)d_in[1];
    const float* b1       = (const float*)d_in[2];
    const float* W2       = (const float*)d_in[3];
    const float* b2       = (const float*)d_in[4];
    const int*   flat_idx = (const int*)d_in[5];
    const int*   seg      = (const int*)d_in[6];
    float*       out      = (float*)d_out;

    const int n_tok = in_sizes[5];
    const int n_img = out_size / DOUT;
    const int mpad  = ((n_tok + 127) / 128) * 128;

    __half *xh, *w1h, *w2h, *hh;
    float *sbuf, *pbuf;
    cudaGetSymbolAddress((void**)&xh,  g_X);
    cudaGetSymbolAddress((void**)&w1h, g_W1h);
    cudaGetSymbolAddress((void**)&w2h, g_W2h);
    cudaGetSymbolAddress((void**)&hh,  g_H);
    cudaGetSymbolAddress((void**)&sbuf, g_S);
    cudaGetSymbolAddress((void**)&pbuf, g_P);

    cudaFuncSetAttribute(mma_gemm<HDIM, true>,
                         cudaFuncAttributeMaxDynamicSharedMemorySize, GEMM_SMEM);
    cudaFuncSetAttribute(mma_gemm<DMID, false>,
                         cudaFuncAttributeMaxDynamicSharedMemorySize, GEMM_SMEM);

    // 1) conversions
    {
        long long t4 = (long long)mpad * HDIM / 4;
        conv_fp16<<<(unsigned)((t4 + 255) / 256), 256>>>(hidden, flat_idx, n_tok, t4, HDIM, xh);
        long long w1t = (long long)DMID * HDIM / 4;
        conv_fp16<<<(unsigned)((w1t + 255) / 256), 256>>>(W1, nullptr, DMID, w1t, HDIM, w1h);
        long long w2t = (long long)DOUT * DMID / 4;
        conv_fp16<<<(unsigned)((w2t + 255) / 256), 256>>>(W2, nullptr, DOUT, w2t, DMID, w2h);
    }
    // 2) GEMM1 + bias + mish -> H (fp16)
    {
        dim3 g(DMID / 256, mpad / 128);
        mma_gemm<HDIM, true><<<g, 512, GEMM_SMEM>>>(xh, w1h, b1, hh, nullptr, DMID);
    }
    // 3) GEMM2 + bias -> S (fp32)
    {
        dim3 g(DOUT / 256, mpad / 128);
        mma_gemm<DMID, false><<<g, 512, GEMM_SMEM>>>(hh, w2h, b2, nullptr, sbuf, DOUT);
    }
    // 4) pooling (2-phase deterministic)
    {
        dim3 gp(n_img, PCHUNK / 4);
        pool_partial<<<gp, 1024>>>(sbuf, seg, n_tok, pbuf);
        pool_final<<<n_img, 256>>>(pbuf, out);
    }
}